// round 1
// baseline (speedup 1.0000x reference)
#include <cuda_runtime.h>
#include <math.h>

// ---------------------------------------------------------------------------
// TokenEmbedding: content embeddings + positional maps via binary-path
// products of two orthogonal generators G[b] = expm(P_b^T - P_b).
//
// Output layout (float32, matching reference tuple (content, maps)):
//   [0, n_tokens*64)            content [B,S,64]
//   [n_tokens*64, ...)          maps    [B,S,64,64]
// ---------------------------------------------------------------------------

#define NPOS 2048
#define MSZ  4096   // 64*64 floats per matrix

// Scratch: position-map table (32 MB) and the two generators.
__device__ __align__(16) float g_M[NPOS * MSZ];
__device__ __align__(16) float g_G[2 * MSZ];

// ---------------------------------------------------------------------------
// Block-level 64x64x64 fp32 matmul: C = A @ B.  256 threads, 4x4 tile/thread.
// A, B row-major (shared), C row-major (shared or global). No aliasing.
// Caller handles __syncthreads around it.
// ---------------------------------------------------------------------------
__device__ __forceinline__ void mm64(float* __restrict__ C,
                                     const float* __restrict__ A,
                                     const float* __restrict__ B) {
    const int tid = threadIdx.x;
    const int ty = tid >> 4;
    const int tx = tid & 15;
    const int r0 = ty << 2;
    const int c0 = tx << 2;
    float acc[4][4];
#pragma unroll
    for (int r = 0; r < 4; r++)
#pragma unroll
        for (int c = 0; c < 4; c++) acc[r][c] = 0.0f;

#pragma unroll
    for (int j0 = 0; j0 < 64; j0 += 4) {
        float4 a[4], b[4];
#pragma unroll
        for (int r = 0; r < 4; r++)
            a[r] = *(const float4*)(A + (r0 + r) * 64 + j0);
#pragma unroll
        for (int jj = 0; jj < 4; jj++)
            b[jj] = *(const float4*)(B + (j0 + jj) * 64 + c0);
#pragma unroll
        for (int r = 0; r < 4; r++) {
            acc[r][0] += a[r].x * b[0].x; acc[r][1] += a[r].x * b[0].y;
            acc[r][2] += a[r].x * b[0].z; acc[r][3] += a[r].x * b[0].w;
            acc[r][0] += a[r].y * b[1].x; acc[r][1] += a[r].y * b[1].y;
            acc[r][2] += a[r].y * b[1].z; acc[r][3] += a[r].y * b[1].w;
            acc[r][0] += a[r].z * b[2].x; acc[r][1] += a[r].z * b[2].y;
            acc[r][2] += a[r].z * b[2].z; acc[r][3] += a[r].z * b[2].w;
            acc[r][0] += a[r].w * b[3].x; acc[r][1] += a[r].w * b[3].y;
            acc[r][2] += a[r].w * b[3].z; acc[r][3] += a[r].w * b[3].w;
        }
    }
#pragma unroll
    for (int r = 0; r < 4; r++) {
        float4 v = make_float4(acc[r][0], acc[r][1], acc[r][2], acc[r][3]);
        *(float4*)(C + (r0 + r) * 64 + c0) = v;
    }
}

// ---------------------------------------------------------------------------
// Kernel 1: expm. Block b computes G[b] = expm(P_b^T - P_b).
// Order-9 Taylor (Paterson-Stockmeyer, 4 matmuls) + scaling/squaring.
// Also seeds M[0] = M[1] = I.
// Dynamic smem: 5 * 16 KB = 80 KB (B, B2, B3, X, Y).
// ---------------------------------------------------------------------------
__global__ void __launch_bounds__(256, 1)
expm_kernel(const float* __restrict__ prim_raw) {
    extern __shared__ float sm[];
    float* Bb = sm;
    float* B2 = sm + MSZ;
    float* B3 = sm + 2 * MSZ;
    float* X  = sm + 3 * MSZ;
    float* Y  = sm + 4 * MSZ;
    __shared__ float colsum[64];
    __shared__ int s_sh;

    const int b = blockIdx.x;
    const int tid = threadIdx.x;
    const float* P = prim_raw + b * MSZ;

    // A = P^T - P  (skew-symmetric; expm(A) == prims[b]^T directly)
    for (int t = tid; t < MSZ; t += 256) {
        int i = t >> 6, j = t & 63;
        Bb[t] = P[j * 64 + i] - P[t];
    }
    __syncthreads();

    // 1-norm for scaling
    if (tid < 64) {
        float s = 0.0f;
        for (int i = 0; i < 64; i++) s += fabsf(Bb[i * 64 + tid]);
        colsum[tid] = s;
    }
    __syncthreads();
    if (tid == 0) {
        float nm = 0.0f;
        for (int j = 0; j < 64; j++) nm = fmaxf(nm, colsum[j]);
        int s = 0;
        while (nm > 1.0f && s < 14) { nm *= 0.5f; s++; }
        s_sh = s;
    }
    __syncthreads();
    const int s = s_sh;
    const float scale = ldexpf(1.0f, -s);
    for (int t = tid; t < MSZ; t += 256) Bb[t] *= scale;
    __syncthreads();

    mm64(B2, Bb, Bb);
    __syncthreads();
    mm64(B3, Bb, B2);
    __syncthreads();

    // X = S2 + c9*B3 ;  S2 = I/6! + B/7! + B2/8!, c9 = 1/9!
    for (int t = tid; t < MSZ; t += 256) {
        int i = t >> 6, j = t & 63;
        float d = (i == j) ? (1.0f / 720.0f) : 0.0f;
        X[t] = d + Bb[t] * (1.0f / 5040.0f) + B2[t] * (1.0f / 40320.0f)
                 + B3[t] * (1.0f / 362880.0f);
    }
    __syncthreads();
    mm64(Y, B3, X);
    __syncthreads();
    // X = S1 + B3*X ;  S1 = I/3! + B/4! + B2/5!
    for (int t = tid; t < MSZ; t += 256) {
        int i = t >> 6, j = t & 63;
        float d = (i == j) ? (1.0f / 6.0f) : 0.0f;
        X[t] = d + Bb[t] * (1.0f / 24.0f) + B2[t] * (1.0f / 120.0f) + Y[t];
    }
    __syncthreads();
    mm64(Y, B3, X);
    __syncthreads();
    // X = S0 + B3*X ;  S0 = I + B + B2/2
    for (int t = tid; t < MSZ; t += 256) {
        int i = t >> 6, j = t & 63;
        float d = (i == j) ? 1.0f : 0.0f;
        X[t] = d + Bb[t] + B2[t] * 0.5f + Y[t];
    }
    __syncthreads();

    // squarings
    float* Xp = X;
    float* Yp = Y;
    for (int k = 0; k < s; k++) {
        mm64(Yp, Xp, Xp);
        __syncthreads();
        float* tp = Xp; Xp = Yp; Yp = tp;
    }

    // Emit G[b]; seed M[0] and M[1] with identity (block 0 -> M[0], block 1 -> M[1]).
    for (int t = tid; t < MSZ; t += 256) {
        g_G[b * MSZ + t] = Xp[t];
        int i = t >> 6, j = t & 63;
        g_M[b * MSZ + t] = (i == j) ? 1.0f : 0.0f;
    }
}

// ---------------------------------------------------------------------------
// Kernel 2: M[p] for p in [2,64) by direct chain M = G[b0]*G[b1]*...
// One block per position; at most 4 sequential matmuls (bitlen<=6).
// Dynamic smem: 3 * 16 KB.
// ---------------------------------------------------------------------------
__global__ void __launch_bounds__(256, 1)
table_small_kernel() {
    extern __shared__ float sm[];
    float* X  = sm;
    float* Gs = sm + MSZ;
    float* Y  = sm + 2 * MSZ;
    const int p = blockIdx.x + 2;
    const int tid = threadIdx.x;
    const int m = 32 - __clz(p);  // bit length; factor bits b0..b_{m-2}

    for (int t = tid; t < MSZ; t += 256) X[t] = g_G[(p & 1) * MSZ + t];
    __syncthreads();
    for (int st = 1; st <= m - 2; st++) {
        const int bit = (p >> st) & 1;
        for (int t = tid; t < MSZ; t += 256) Gs[t] = g_G[bit * MSZ + t];
        __syncthreads();
        mm64(Y, X, Gs);
        __syncthreads();
        float* tp = X; X = Y; Y = tp;
    }
    for (int t = tid; t < MSZ; t += 256) g_M[p * MSZ + t] = X[t];
}

// ---------------------------------------------------------------------------
// Kernel 3: M[p] for p in [64,2048):  M[p] = M[32|(p&31)] @ M[p>>5].
// Both operands already computed by kernel 2 (indices in [2,64)).
// One matmul per block. Dynamic smem: 2 * 16 KB.
// ---------------------------------------------------------------------------
__global__ void __launch_bounds__(256, 1)
table_big_kernel() {
    extern __shared__ float sm[];
    float* A = sm;
    float* B = sm + MSZ;
    const int p = blockIdx.x + 64;
    const int tid = threadIdx.x;
    const float* ML = g_M + (size_t)((p & 31) | 32) * MSZ;
    const float* MR = g_M + (size_t)(p >> 5) * MSZ;
    for (int t = tid; t < MSZ; t += 256) { A[t] = ML[t]; B[t] = MR[t]; }
    __syncthreads();
    mm64(g_M + (size_t)p * MSZ, A, B);
}

// ---------------------------------------------------------------------------
// Kernel 4: gather. One block per token: copy M[pos] into the maps output and
// compute the masked content embedding.
// ---------------------------------------------------------------------------
__global__ void __launch_bounds__(256, 1)
gather_kernel(const int* __restrict__ token_types,
              const int* __restrict__ token_values,
              const int* __restrict__ node_positions,
              const float* __restrict__ embed_table,
              float* __restrict__ out,
              int maps_off) {
    const int token = blockIdx.x;
    const int tid = threadIdx.x;
    const int p = node_positions[token];

    const float4* src = (const float4*)(g_M + (size_t)p * MSZ);
    float4* dst = (float4*)(out + (size_t)maps_off + (size_t)token * MSZ);
#pragma unroll
    for (int t = tid; t < MSZ / 4; t += 256) dst[t] = src[t];

    if (tid < 64) {
        const int T = token_types[token];
        const int V = token_values[token];
        int idx;
        bool valid = true;
        if (T == 0)      idx = 0;
        else if (T == 1) idx = V + 1;
        else if (T == 2) idx = V + 5;
        else if (T == 4) idx = 8;
        else if (T == 3 && V == -1) idx = 10;
        else { idx = 0; valid = false; }
        out[(size_t)token * 64 + tid] = valid ? embed_table[idx * 64 + tid] : 0.0f;
    }
}

// ---------------------------------------------------------------------------
extern "C" void kernel_launch(void* const* d_in, const int* in_sizes, int n_in,
                              void* d_out, int out_size) {
    const int*   token_types  = (const int*)d_in[0];
    const int*   token_values = (const int*)d_in[1];
    const int*   node_pos     = (const int*)d_in[2];
    const float* embed_table  = (const float*)d_in[3];
    const float* prim_raw     = (const float*)d_in[4];
    float* out = (float*)d_out;

    const int n_tokens = in_sizes[0];          // B*S = 4096
    const int maps_off = n_tokens * 64;        // content block size

    cudaFuncSetAttribute(expm_kernel,
                         cudaFuncAttributeMaxDynamicSharedMemorySize, 5 * MSZ * 4);
    cudaFuncSetAttribute(table_small_kernel,
                         cudaFuncAttributeMaxDynamicSharedMemorySize, 3 * MSZ * 4);
    cudaFuncSetAttribute(table_big_kernel,
                         cudaFuncAttributeMaxDynamicSharedMemorySize, 2 * MSZ * 4);

    expm_kernel<<<2, 256, 5 * MSZ * 4>>>(prim_raw);
    table_small_kernel<<<62, 256, 3 * MSZ * 4>>>();
    table_big_kernel<<<NPOS - 64, 256, 2 * MSZ * 4>>>();
    gather_kernel<<<n_tokens, 256>>>(token_types, token_values, node_pos,
                                     embed_table, out, maps_off);
}

// round 2
// speedup vs baseline: 1.1743x; 1.1743x over previous
#include <cuda_runtime.h>
#include <math.h>

// ---------------------------------------------------------------------------
// TokenEmbedding: content embeddings + positional maps via binary-path
// products of two orthogonal generators G[b] = expm(P_b^T - P_b).
// All 64x64 matmuls now run on tensor cores via 3xTF32 mma.sync.
//
// Output layout (float32):
//   [0, n_tokens*64)   content [B,S,64]
//   [n_tokens*64, ...) maps    [B,S,64,64]
// ---------------------------------------------------------------------------

#define NPOS 2048
#define MSZ  4096      // 64*64 floats (dense global matrices)
#define SMS  66        // padded shared-memory row stride (floats)
#define SMAT (64 * SMS)

__device__ __align__(16) float g_M[NPOS * MSZ];
__device__ __align__(16) float g_G[2 * MSZ];

// ---------------------------------------------------------------------------
// tf32 helpers
// ---------------------------------------------------------------------------
__device__ __forceinline__ unsigned f2tf32(float x) {
    unsigned r;
    asm("cvt.rna.tf32.f32 %0, %1;" : "=r"(r) : "f"(x));
    return r;
}

__device__ __forceinline__ void mma_tf32(float& c0, float& c1, float& c2, float& c3,
                                         unsigned a0, unsigned a1, unsigned a2, unsigned a3,
                                         unsigned b0, unsigned b1) {
    asm volatile(
        "mma.sync.aligned.m16n8k8.row.col.f32.tf32.tf32.f32 "
        "{%0,%1,%2,%3}, {%4,%5,%6,%7}, {%8,%9}, {%0,%1,%2,%3};\n"
        : "+f"(c0), "+f"(c1), "+f"(c2), "+f"(c3)
        : "r"(a0), "r"(a1), "r"(a2), "r"(a3), "r"(b0), "r"(b1));
}

// ---------------------------------------------------------------------------
// Block-level 64x64x64 matmul on tensor cores, 3xTF32 (fp32-comparable).
// A, B in shared memory with row stride SMS. C written with row stride CS
// (can be shared with CS=SMS or global with CS=64). 256 threads = 8 warps;
// warp w computes C[(w&3)*16 .. +16, (w>>2)*32 .. +32].
// Caller handles __syncthreads around it.
// ---------------------------------------------------------------------------
__device__ __forceinline__ void mm64(float* __restrict__ C, int CS,
                                     const float* __restrict__ A,
                                     const float* __restrict__ B) {
    const int lane = threadIdx.x & 31;
    const int w    = threadIdx.x >> 5;
    const int g    = lane >> 2;       // group id (0..7)
    const int t    = lane & 3;        // thread-in-group (0..3)
    const int m0   = (w & 3) * 16;
    const int n0   = (w >> 2) * 32;

    float acc[4][4];
#pragma unroll
    for (int nt = 0; nt < 4; nt++)
#pragma unroll
        for (int c = 0; c < 4; c++) acc[nt][c] = 0.0f;

#pragma unroll
    for (int k0 = 0; k0 < 64; k0 += 8) {
        // A fragment (m16 x k8): rows m0+g, m0+g+8; cols k0+t, k0+t+4
        float af0 = A[(m0 + g)     * SMS + k0 + t];
        float af1 = A[(m0 + g + 8) * SMS + k0 + t];
        float af2 = A[(m0 + g)     * SMS + k0 + t + 4];
        float af3 = A[(m0 + g + 8) * SMS + k0 + t + 4];
        unsigned ah0 = f2tf32(af0), ah1 = f2tf32(af1);
        unsigned ah2 = f2tf32(af2), ah3 = f2tf32(af3);
        unsigned al0 = f2tf32(af0 - __uint_as_float(ah0));
        unsigned al1 = f2tf32(af1 - __uint_as_float(ah1));
        unsigned al2 = f2tf32(af2 - __uint_as_float(ah2));
        unsigned al3 = f2tf32(af3 - __uint_as_float(ah3));

#pragma unroll
        for (int nt = 0; nt < 4; nt++) {
            const int nc = n0 + nt * 8 + g;
            // B fragment (k8 x n8): element (k, n) = B[k*SMS + n]
            float bf0 = B[(k0 + t)     * SMS + nc];
            float bf1 = B[(k0 + t + 4) * SMS + nc];
            unsigned bh0 = f2tf32(bf0), bh1 = f2tf32(bf1);
            unsigned bl0 = f2tf32(bf0 - __uint_as_float(bh0));
            unsigned bl1 = f2tf32(bf1 - __uint_as_float(bh1));

            mma_tf32(acc[nt][0], acc[nt][1], acc[nt][2], acc[nt][3],
                     ah0, ah1, ah2, ah3, bh0, bh1);
            mma_tf32(acc[nt][0], acc[nt][1], acc[nt][2], acc[nt][3],
                     ah0, ah1, ah2, ah3, bl0, bl1);
            mma_tf32(acc[nt][0], acc[nt][1], acc[nt][2], acc[nt][3],
                     al0, al1, al2, al3, bh0, bh1);
        }
    }

    // Epilogue: c0 at (g, 2t), c1 (g, 2t+1), c2 (g+8, 2t), c3 (g+8, 2t+1)
#pragma unroll
    for (int nt = 0; nt < 4; nt++) {
        const int col = n0 + nt * 8 + 2 * t;
        *(float2*)(C + (m0 + g)     * CS + col) = make_float2(acc[nt][0], acc[nt][1]);
        *(float2*)(C + (m0 + g + 8) * CS + col) = make_float2(acc[nt][2], acc[nt][3]);
    }
}

// ---------------------------------------------------------------------------
// Kernel 1: expm. Block b computes G[b] = expm(P_b^T - P_b).
// Order-9 Taylor (Paterson-Stockmeyer) + scaling/squaring. Seeds M[0]=M[1]=I.
// Dynamic smem: 5 * SMAT floats = 84,480 B.
// ---------------------------------------------------------------------------
__global__ void __launch_bounds__(256, 1)
expm_kernel(const float* __restrict__ prim_raw) {
    extern __shared__ float sm[];
    float* Bb = sm;
    float* B2 = sm + SMAT;
    float* B3 = sm + 2 * SMAT;
    float* X  = sm + 3 * SMAT;
    float* Y  = sm + 4 * SMAT;
    __shared__ float colsum[64];
    __shared__ int s_sh;

    const int b = blockIdx.x;
    const int tid = threadIdx.x;
    const float* P = prim_raw + b * MSZ;

    for (int tidx = tid; tidx < MSZ; tidx += 256) {
        int i = tidx >> 6, j = tidx & 63;
        Bb[i * SMS + j] = P[j * 64 + i] - P[tidx];
    }
    __syncthreads();

    if (tid < 64) {
        float s = 0.0f;
        for (int i = 0; i < 64; i++) s += fabsf(Bb[i * SMS + tid]);
        colsum[tid] = s;
    }
    __syncthreads();
    if (tid == 0) {
        float nm = 0.0f;
        for (int j = 0; j < 64; j++) nm = fmaxf(nm, colsum[j]);
        int s = 0;
        while (nm > 1.0f && s < 14) { nm *= 0.5f; s++; }
        s_sh = s;
    }
    __syncthreads();
    const int s = s_sh;
    const float scale = ldexpf(1.0f, -s);
    for (int tidx = tid; tidx < MSZ; tidx += 256) {
        int i = tidx >> 6, j = tidx & 63;
        Bb[i * SMS + j] *= scale;
    }
    __syncthreads();

    mm64(B2, SMS, Bb, Bb);
    __syncthreads();
    mm64(B3, SMS, Bb, B2);
    __syncthreads();

    // X = I/720 + B/5040 + B2/40320 + B3/362880
    for (int tidx = tid; tidx < MSZ; tidx += 256) {
        int i = tidx >> 6, j = tidx & 63;
        int k = i * SMS + j;
        float d = (i == j) ? (1.0f / 720.0f) : 0.0f;
        X[k] = d + Bb[k] * (1.0f / 5040.0f) + B2[k] * (1.0f / 40320.0f)
                 + B3[k] * (1.0f / 362880.0f);
    }
    __syncthreads();
    mm64(Y, SMS, B3, X);
    __syncthreads();
    for (int tidx = tid; tidx < MSZ; tidx += 256) {
        int i = tidx >> 6, j = tidx & 63;
        int k = i * SMS + j;
        float d = (i == j) ? (1.0f / 6.0f) : 0.0f;
        X[k] = d + Bb[k] * (1.0f / 24.0f) + B2[k] * (1.0f / 120.0f) + Y[k];
    }
    __syncthreads();
    mm64(Y, SMS, B3, X);
    __syncthreads();
    for (int tidx = tid; tidx < MSZ; tidx += 256) {
        int i = tidx >> 6, j = tidx & 63;
        int k = i * SMS + j;
        float d = (i == j) ? 1.0f : 0.0f;
        X[k] = d + Bb[k] + B2[k] * 0.5f + Y[k];
    }
    __syncthreads();

    float* Xp = X;
    float* Yp = Y;
    for (int k = 0; k < s; k++) {
        mm64(Yp, SMS, Xp, Xp);
        __syncthreads();
        float* tp = Xp; Xp = Yp; Yp = tp;
    }

    for (int tidx = tid; tidx < MSZ; tidx += 256) {
        int i = tidx >> 6, j = tidx & 63;
        g_G[b * MSZ + tidx] = Xp[i * SMS + j];
        g_M[b * MSZ + tidx] = (i == j) ? 1.0f : 0.0f;
    }
}

// ---------------------------------------------------------------------------
// Kernel 2: M[p] for p in [2,64): chain of G factors (<=4 matmuls).
// Dynamic smem: 3 * SMAT floats.
// ---------------------------------------------------------------------------
__global__ void __launch_bounds__(256, 1)
table_small_kernel() {
    extern __shared__ float sm[];
    float* X  = sm;
    float* Gs = sm + SMAT;
    float* Y  = sm + 2 * SMAT;
    const int p = blockIdx.x + 2;
    const int tid = threadIdx.x;
    const int m = 32 - __clz(p);

    for (int tidx = tid; tidx < MSZ; tidx += 256) {
        int i = tidx >> 6, j = tidx & 63;
        X[i * SMS + j] = g_G[(p & 1) * MSZ + tidx];
    }
    __syncthreads();
    for (int st = 1; st <= m - 2; st++) {
        const int bit = (p >> st) & 1;
        for (int tidx = tid; tidx < MSZ; tidx += 256) {
            int i = tidx >> 6, j = tidx & 63;
            Gs[i * SMS + j] = g_G[bit * MSZ + tidx];
        }
        __syncthreads();
        mm64(Y, SMS, X, Gs);
        __syncthreads();
        float* tp = X; X = Y; Y = tp;
    }
    for (int tidx = tid; tidx < MSZ; tidx += 256) {
        int i = tidx >> 6, j = tidx & 63;
        g_M[(size_t)p * MSZ + tidx] = X[i * SMS + j];
    }
}

// ---------------------------------------------------------------------------
// Kernel 3: M[p] for p in [64,2048): M[p] = M[32|(p&31)] @ M[p>>5].
// Dynamic smem: 2 * SMAT floats. C written straight to global (stride 64).
// ---------------------------------------------------------------------------
__global__ void __launch_bounds__(256, 1)
table_big_kernel() {
    extern __shared__ float sm[];
    float* A = sm;
    float* B = sm + SMAT;
    const int p = blockIdx.x + 64;
    const int tid = threadIdx.x;
    const float* ML = g_M + (size_t)((p & 31) | 32) * MSZ;
    const float* MR = g_M + (size_t)(p >> 5) * MSZ;
    for (int tidx = tid; tidx < MSZ; tidx += 256) {
        int i = tidx >> 6, j = tidx & 63;
        A[i * SMS + j] = ML[tidx];
        B[i * SMS + j] = MR[tidx];
    }
    __syncthreads();
    mm64(g_M + (size_t)p * MSZ, 64, A, B);
}

// ---------------------------------------------------------------------------
// Kernel 4: gather. Copy M[pos] into maps output (streaming stores) and
// compute the masked content embedding.
// ---------------------------------------------------------------------------
__global__ void __launch_bounds__(256, 1)
gather_kernel(const int* __restrict__ token_types,
              const int* __restrict__ token_values,
              const int* __restrict__ node_positions,
              const float* __restrict__ embed_table,
              float* __restrict__ out,
              int maps_off) {
    const int token = blockIdx.x;
    const int tid = threadIdx.x;
    const int p = node_positions[token];

    const float4* src = (const float4*)(g_M + (size_t)p * MSZ);
    float4* dst = (float4*)(out + (size_t)maps_off + (size_t)token * MSZ);
    float4 v[4];
#pragma unroll
    for (int i = 0; i < 4; i++) v[i] = __ldg(&src[tid + i * 256]);
#pragma unroll
    for (int i = 0; i < 4; i++) __stcs(&dst[tid + i * 256], v[i]);

    if (tid < 64) {
        const int T = token_types[token];
        const int V = token_values[token];
        int idx;
        bool valid = true;
        if (T == 0)      idx = 0;
        else if (T == 1) idx = V + 1;
        else if (T == 2) idx = V + 5;
        else if (T == 4) idx = 8;
        else if (T == 3 && V == -1) idx = 10;
        else { idx = 0; valid = false; }
        out[(size_t)token * 64 + tid] = valid ? embed_table[idx * 64 + tid] : 0.0f;
    }
}

// ---------------------------------------------------------------------------
extern "C" void kernel_launch(void* const* d_in, const int* in_sizes, int n_in,
                              void* d_out, int out_size) {
    const int*   token_types  = (const int*)d_in[0];
    const int*   token_values = (const int*)d_in[1];
    const int*   node_pos     = (const int*)d_in[2];
    const float* embed_table  = (const float*)d_in[3];
    const float* prim_raw     = (const float*)d_in[4];
    float* out = (float*)d_out;

    const int n_tokens = in_sizes[0];
    const int maps_off = n_tokens * 64;

    cudaFuncSetAttribute(expm_kernel,
                         cudaFuncAttributeMaxDynamicSharedMemorySize, 5 * SMAT * 4);
    cudaFuncSetAttribute(table_small_kernel,
                         cudaFuncAttributeMaxDynamicSharedMemorySize, 3 * SMAT * 4);
    cudaFuncSetAttribute(table_big_kernel,
                         cudaFuncAttributeMaxDynamicSharedMemorySize, 2 * SMAT * 4);

    expm_kernel<<<2, 256, 5 * SMAT * 4>>>(prim_raw);
    table_small_kernel<<<62, 256, 3 * SMAT * 4>>>();
    table_big_kernel<<<NPOS - 64, 256, 2 * SMAT * 4>>>();
    gather_kernel<<<n_tokens, 256>>>(token_types, token_values, node_pos,
                                     embed_table, out, maps_off);
}